// round 15
// baseline (speedup 1.0000x reference)
#include <cuda_runtime.h>
#include <cuda_bf16.h>
#include <cuda_fp16.h>
#include <cstdint>

// ---------------------------------------------------------------------------
// Problem constants
// ---------------------------------------------------------------------------
#define B_ 2
#define T_ 2048
#define C_ 1024
#define H_ 16
#define D_ 64
#define M_ROWS (B_ * T_)     // 4096
#define N_QKV  (3 * C_)      // 3072

// softmax scale * log2(e) folded into Q: (1/8) * 1.4426950408889634
#define QS 0.18033688011112042f

// Scratch (__device__ globals; allocation-free rule)
__device__ __half g_xh[(size_t)M_ROWS * C_];        // activations fp16 (x, then att)
__device__ __half g_wt[(size_t)N_QKV * C_];         // W_qkv^T fp16 [N,K]
__device__ __half g_wt2[(size_t)C_ * C_];           // W_proj^T fp16 [N,K]
// per-head fp16 [B,H,T,D]
__device__ __half g_qh[(size_t)B_ * H_ * T_ * D_];  // q (pre-scaled by QS)
__device__ __half g_kh[(size_t)B_ * H_ * T_ * D_];
__device__ __half g_vh[(size_t)B_ * H_ * T_ * D_];

// ---------------------------------------------------------------------------
// Warp MMA / async-copy helpers (sm_80+ baseline)
// ---------------------------------------------------------------------------
__device__ __forceinline__ uint32_t smem_to_u32(const void* p) {
    uint32_t a;
    asm("{ .reg .u64 t; cvta.to.shared.u64 t, %1; cvt.u32.u64 %0, t; }"
        : "=r"(a) : "l"(p));
    return a;
}
__device__ __forceinline__ void ldsm_x4(uint32_t (&r)[4], uint32_t addr) {
    asm volatile("ldmatrix.sync.aligned.m8n8.x4.shared.b16 {%0,%1,%2,%3}, [%4];"
                 : "=r"(r[0]), "=r"(r[1]), "=r"(r[2]), "=r"(r[3]) : "r"(addr));
}
__device__ __forceinline__ void ldsm_x4_t(uint32_t (&r)[4], uint32_t addr) {
    asm volatile("ldmatrix.sync.aligned.m8n8.x4.trans.shared.b16 {%0,%1,%2,%3}, [%4];"
                 : "=r"(r[0]), "=r"(r[1]), "=r"(r[2]), "=r"(r[3]) : "r"(addr));
}
__device__ __forceinline__ void mma16816h(float (&d)[4],
                                          const uint32_t (&a)[4],
                                          const uint32_t b0, const uint32_t b1) {
    asm volatile(
        "mma.sync.aligned.m16n8k16.row.col.f32.f16.f16.f32 "
        "{%0,%1,%2,%3}, {%4,%5,%6,%7}, {%8,%9}, {%0,%1,%2,%3};"
        : "+f"(d[0]), "+f"(d[1]), "+f"(d[2]), "+f"(d[3])
        : "r"(a[0]), "r"(a[1]), "r"(a[2]), "r"(a[3]), "r"(b0), "r"(b1));
}
__device__ __forceinline__ uint32_t swz(uint32_t off) {
    return off ^ ((off >> 3) & 0x70);
}
__device__ __forceinline__ float ex2(float x) {
    float y; asm("ex2.approx.ftz.f32 %0, %1;" : "=f"(y) : "f"(x)); return y;
}
__device__ __forceinline__ void cp16(uint32_t dst, const void* src) {
    asm volatile("cp.async.ca.shared.global [%0], [%1], 16;" :: "r"(dst), "l"(src));
}
__device__ __forceinline__ void cp_commit() {
    asm volatile("cp.async.commit_group;" ::: "memory");
}
template<int N> __device__ __forceinline__ void cp_wait() {
    asm volatile("cp.async.wait_group %0;" :: "n"(N) : "memory");
}

// ---------------------------------------------------------------------------
// Fused prepass (R13): x->fp16, w_qkv->W^T, w_proj->W^T in one kernel.
// ---------------------------------------------------------------------------
#define PRE_XBLOCKS   4096
#define PRE_QKVBLOCKS 3072
#define PRE_PROJBLOCKS 1024
#define PRE_TOTAL (PRE_XBLOCKS + PRE_QKVBLOCKS + PRE_PROJBLOCKS)

__global__ __launch_bounds__(256)
void prepass(const float* __restrict__ x,
             const float* __restrict__ w_qkv, const float* __restrict__ w_proj,
             __half* __restrict__ xh,
             __half* __restrict__ wt_qkv, __half* __restrict__ wt_proj)
{
    const int bid = blockIdx.x;

    if (bid < PRE_XBLOCKS) {
        int i = bid * 256 + threadIdx.x;
        float4 v = ((const float4*)x)[i];
        ((__half2*)xh)[i * 2 + 0] = __floats2half2_rn(v.x, v.y);
        ((__half2*)xh)[i * 2 + 1] = __floats2half2_rn(v.z, v.w);
        return;
    }

    const float* W;
    __half* Wt;
    int N, tileIdx;
    if (bid < PRE_XBLOCKS + PRE_QKVBLOCKS) {
        W = w_qkv; Wt = wt_qkv; N = N_QKV;
        tileIdx = bid - PRE_XBLOCKS;
    } else {
        W = w_proj; Wt = wt_proj; N = C_;
        tileIdx = bid - PRE_XBLOCKS - PRE_QKVBLOCKS;
    }
    const int ntilesN = N / 32;
    const int n0 = (tileIdx % ntilesN) * 32;
    const int k0 = (tileIdx / ntilesN) * 32;

    __shared__ float tile[32][33];
    const int tx = threadIdx.x & 31;
    const int ty = threadIdx.x >> 5;
#pragma unroll
    for (int r = ty; r < 32; r += 8)
        tile[r][tx] = W[(size_t)(k0 + r) * N + n0 + tx];
    __syncthreads();
#pragma unroll
    for (int r = ty; r < 32; r += 8)
        Wt[(size_t)(n0 + r) * C_ + k0 + tx] = __float2half_rn(tile[tx][r]);
}

// ---------------------------------------------------------------------------
// HMMA GEMM fp16 single-term, 256 threads / 8 warps, warp tile 64x32.
// __launch_bounds__(256, 2). Used for the QKV GEMM (MODE 1 scatter).
// ---------------------------------------------------------------------------
#define SM_A  0
#define SM_B  16384
#define SM_STAGE 32768
#define SM_TOTAL (3 * SM_STAGE)     // 98304

__global__ __launch_bounds__(256, 2)
void gemm_qkv(const __half* __restrict__ A, const __half* __restrict__ Bt,
              const float* __restrict__ bias,
              __half* __restrict__ qh, __half* __restrict__ kh,
              __half* __restrict__ vh,
              int M, int N, int K)
{
    extern __shared__ char smem[];
    const uint32_t sb = smem_to_u32(smem);

    const int tid  = threadIdx.x;
    const int wid  = tid >> 5;
    const int lane = tid & 31;
    const int rowBase = blockIdx.y * 128;
    const int colBase = blockIdx.x * 128;

    const int warp_m = wid & 1;        // 2 x 64-row halves
    const int warp_n = wid >> 1;       // 4 x 32-col quarters

    float acc[4][4][4];
#pragma unroll
    for (int i = 0; i < 4; i++)
#pragma unroll
        for (int j = 0; j < 4; j++)
#pragma unroll
            for (int r = 0; r < 4; r++) acc[i][j][r] = 0.f;

    const int a_r  = warp_m * 64 + (lane & 15);
    const int a_cb = (lane >> 4) << 4;
    const int g    = lane >> 3;
    const int b_r  = warp_n * 32 + ((g >> 1) << 3) + (lane & 7);
    const int b_cb = (g & 1) << 4;

    int ld_r[4], ld_cb[4];
    uint32_t ld_sw[4];
#pragma unroll
    for (int it = 0; it < 4; it++) {
        int idx = it * 256 + tid;
        ld_r[it]  = idx >> 3;
        ld_cb[it] = (idx & 7) << 4;
        ld_sw[it] = swz((uint32_t)(ld_r[it] * 128 + ld_cb[it]));
    }

    auto issue = [&](int ch, int st) {
        const int k0 = ch * 64;
        const uint32_t sbase = sb + st * SM_STAGE;
#pragma unroll
        for (int it = 0; it < 4; it++) {
            const int r = ld_r[it], cb = ld_cb[it];
            const uint32_t sw = ld_sw[it];
            cp16(sbase + SM_A + sw, (const char*)(A  + (size_t)(rowBase + r) * K + k0) + cb);
            cp16(sbase + SM_B + sw, (const char*)(Bt + (size_t)(colBase + r) * K + k0) + cb);
        }
        cp_commit();
    };

    const int nChunks = K / 64;
    issue(0, 0);
    issue(1, 1);

    for (int ch = 0; ch < nChunks; ch++) {
        if (ch + 1 < nChunks) cp_wait<1>(); else cp_wait<0>();
        __syncthreads();
        if (ch + 2 < nChunks) issue(ch + 2, (ch + 2) % 3);

        const uint32_t sbase = sb + (ch % 3) * SM_STAGE;
#pragma unroll
        for (int ks = 0; ks < 4; ks++) {
            const int kb = ks * 32;
            uint32_t af[4][4];
#pragma unroll
            for (int mi = 0; mi < 4; mi++) {
                uint32_t off = swz((uint32_t)((a_r + mi * 16) * 128 + kb + a_cb));
                ldsm_x4(af[mi], sbase + SM_A + off);
            }
            uint32_t bf[2][4];
#pragma unroll
            for (int nt = 0; nt < 2; nt++) {
                uint32_t off = swz((uint32_t)((b_r + nt * 16) * 128 + kb + b_cb));
                ldsm_x4(bf[nt], sbase + SM_B + off);
            }
#pragma unroll
            for (int mi = 0; mi < 4; mi++)
#pragma unroll
                for (int nj = 0; nj < 4; nj++) {
                    const uint32_t* bj = &bf[nj >> 1][(nj & 1) * 2];
                    mma16816h(acc[mi][nj], af[mi], bj[0], bj[1]);
                }
        }
    }

    const int er = rowBase + warp_m * 64 + (lane >> 2);
    const int ec = colBase + warp_n * 32 + (lane & 3) * 2;

#pragma unroll
    for (int nj = 0; nj < 4; nj++) {
        const int c   = ec + nj * 8;
        const int sec = c >> 10;             // 0=q,1=k,2=v
        const int hh  = (c & 1023) >> 6;
        const int dd  = c & 63;
        const float sc = (sec == 0) ? QS : 1.f;
        const float bx = __ldg(bias + c)     * sc;
        const float by = __ldg(bias + c + 1) * sc;
        __half* dp = (sec == 0) ? qh : (sec == 1) ? kh : vh;
#pragma unroll
        for (int mi = 0; mi < 4; mi++) {
#pragma unroll
            for (int half = 0; half < 2; half++) {
                const int r = er + mi * 16 + half * 8;
                const int bb = r >> 11, tt = r & 2047;
                const size_t dst = (((size_t)bb * H_ + hh) * T_ + tt) * D_ + dd;
                float v0 = fmaf(acc[mi][nj][half * 2],     sc, bx);
                float v1 = fmaf(acc[mi][nj][half * 2 + 1], sc, by);
                *(__half2*)(dp + dst) = __floats2half2_rn(v0, v1);
            }
        }
    }
}

// ---------------------------------------------------------------------------
// Proj GEMM: 128x64 CTA tile, 128 threads / 4 warps (warp tile 64x32,
// same 6 LDSM : 16 MMA), 3-stage 72KB, 3 CTAs/SM (uniform 12 warps/SM).
// grid (N/64, M/128) = (16, 32) = 512 CTAs.
// ---------------------------------------------------------------------------
#define PJ_A 0
#define PJ_B 16384
#define PJ_STAGE 24576
#define PJ_TOTAL (3 * PJ_STAGE)     // 73728

__global__ __launch_bounds__(128, 3)
void gemm_proj(const __half* __restrict__ A, const __half* __restrict__ Bt,
               const float* __restrict__ bias, float* __restrict__ Cout,
               int M, int N, int K)
{
    extern __shared__ char smem[];
    const uint32_t sb = smem_to_u32(smem);

    const int tid  = threadIdx.x;
    const int wid  = tid >> 5;
    const int lane = tid & 31;
    const int rowBase = blockIdx.y * 128;
    const int colBase = blockIdx.x * 64;

    const int warp_m = wid & 1;        // 2 x 64-row halves
    const int warp_n = wid >> 1;       // 2 x 32-col halves

    float acc[4][4][4];
#pragma unroll
    for (int i = 0; i < 4; i++)
#pragma unroll
        for (int j = 0; j < 4; j++)
#pragma unroll
            for (int r = 0; r < 4; r++) acc[i][j][r] = 0.f;

    const int a_r  = warp_m * 64 + (lane & 15);
    const int a_cb = (lane >> 4) << 4;
    const int g    = lane >> 3;
    const int b_r  = warp_n * 32 + ((g >> 1) << 3) + (lane & 7);
    const int b_cb = (g & 1) << 4;

    // Load slots: A = 1024 uint4, B = 512 uint4, total 1536 / 128 thr = 12.
    auto issue = [&](int ch, int st) {
        const int k0 = ch * 64;
        const uint32_t sbase = sb + st * PJ_STAGE;
#pragma unroll
        for (int it = 0; it < 12; it++) {
            int idx = it * 128 + tid;            // 0..1535
            if (idx < 1024) {
                int r = idx >> 3, cb = (idx & 7) << 4;
                uint32_t sw = swz((uint32_t)(r * 128 + cb));
                cp16(sbase + PJ_A + sw,
                     (const char*)(A + (size_t)(rowBase + r) * K + k0) + cb);
            } else {
                int j = idx - 1024;              // 0..511
                int r = j >> 3, cb = (j & 7) << 4;
                uint32_t sw = swz((uint32_t)(r * 128 + cb));
                cp16(sbase + PJ_B + sw,
                     (const char*)(Bt + (size_t)(colBase + r) * K + k0) + cb);
            }
        }
        cp_commit();
    };

    const int nChunks = K / 64;
    issue(0, 0);
    issue(1, 1);

    for (int ch = 0; ch < nChunks; ch++) {
        if (ch + 1 < nChunks) cp_wait<1>(); else cp_wait<0>();
        __syncthreads();
        if (ch + 2 < nChunks) issue(ch + 2, (ch + 2) % 3);

        const uint32_t sbase = sb + (ch % 3) * PJ_STAGE;
#pragma unroll
        for (int ks = 0; ks < 4; ks++) {
            const int kb = ks * 32;
            uint32_t af[4][4];
#pragma unroll
            for (int mi = 0; mi < 4; mi++) {
                uint32_t off = swz((uint32_t)((a_r + mi * 16) * 128 + kb + a_cb));
                ldsm_x4(af[mi], sbase + PJ_A + off);
            }
            uint32_t bf[2][4];
#pragma unroll
            for (int nt = 0; nt < 2; nt++) {
                uint32_t off = swz((uint32_t)((b_r + nt * 16) * 128 + kb + b_cb));
                ldsm_x4(bf[nt], sbase + PJ_B + off);
            }
#pragma unroll
            for (int mi = 0; mi < 4; mi++)
#pragma unroll
                for (int nj = 0; nj < 4; nj++) {
                    const uint32_t* bj = &bf[nj >> 1][(nj & 1) * 2];
                    mma16816h(acc[mi][nj], af[mi], bj[0], bj[1]);
                }
        }
    }

    const int er = rowBase + warp_m * 64 + (lane >> 2);
    const int ec = colBase + warp_n * 32 + (lane & 3) * 2;
#pragma unroll
    for (int mi = 0; mi < 4; mi++) {
#pragma unroll
        for (int nj = 0; nj < 4; nj++) {
            const int c = ec + nj * 8;
            const float bx = __ldg(bias + c);
            const float by = __ldg(bias + c + 1);
            float2 v0 = { acc[mi][nj][0] + bx, acc[mi][nj][1] + by };
            float2 v1 = { acc[mi][nj][2] + bx, acc[mi][nj][3] + by };
            *(float2*)(Cout + (size_t)(er + mi * 16) * N + c) = v0;
            *(float2*)(Cout + (size_t)(er + mi * 16 + 8) * N + c) = v1;
        }
    }
}

// ---------------------------------------------------------------------------
// Flash attention (known-good R10/R12): fp16 single-term, m=0 softmax,
// 128 threads / 4 warps, 32 q-rows per warp, Q frags hoisted, per-warp
// masked-tile skip, 64-key tiles, cp.async 3-stage (16KB/stage).
// ---------------------------------------------------------------------------
#define FA_Q 0
#define FA_STAGE0 16384
#define FA_STSZ 16384
#define FA_ST(s) (FA_STAGE0 + (s) * FA_STSZ)
#define FA_K 0
#define FA_V 8192
#define FA_TOTAL (FA_STAGE0 + 3 * FA_STSZ)   // 65536

__global__ __launch_bounds__(128)
void flash_attn(const __half* __restrict__ qh, const __half* __restrict__ kh,
                const __half* __restrict__ vh, __half* __restrict__ att)
{
    extern __shared__ char smem[];
    const uint32_t sb = smem_to_u32(smem);
    const int tid = threadIdx.x, wid = tid >> 5, lane = tid & 31;
    const int h = blockIdx.y, b = blockIdx.z;
    const int qt = gridDim.x - 1 - blockIdx.x;    // big tiles first

    const size_t hoff = ((size_t)b * H_ + h) * T_ * D_;
    const char* qh_p = (const char*)(qh + hoff + (size_t)qt * 128 * D_);
    const char* kh_p = (const char*)(kh + hoff);
    const char* vh_p = (const char*)(vh + hoff);

    auto issue_kv = [&](int kt, int st) {
        const uint32_t sbase = sb + FA_ST(st);
#pragma unroll
        for (int it = 0; it < 4; it++) {
            int idx = it * 128 + tid;            // 0..511
            int r = idx >> 3, cb = (idx & 7) << 4;
            uint32_t sw = swz((uint32_t)(r * 128 + cb));
            size_t go = (size_t)(kt * 64 + r) * 128 + cb;    // bytes
            cp16(sbase + FA_K + sw, kh_p + go);
            cp16(sbase + FA_V + sw, vh_p + go);
        }
        cp_commit();
    };

    const int nkt = 2 * qt + 2;
    issue_kv(0, 0);
    issue_kv(1, 1);

    // Load Q tile into smem (plain stores), then hoist Q frags to registers.
#pragma unroll
    for (int it = 0; it < 8; it++) {
        int idx = it * 128 + tid;
        int r = idx >> 3, cb = (idx & 7) << 4;
        uint32_t sw = swz((uint32_t)(r * 128 + cb));
        *(uint4*)(smem + FA_Q + sw) = *(const uint4*)(qh_p + r * 128 + cb);
    }
    __syncthreads();

    const int a_r  = wid * 32 + (lane & 15);
    const int a_cb = (lane >> 4) << 4;
    uint32_t qf[4][2][4];                 // [ks][mi][reg], loop-invariant
#pragma unroll
    for (int ks = 0; ks < 4; ks++)
#pragma unroll
        for (int mi = 0; mi < 2; mi++) {
            uint32_t off = swz((uint32_t)((a_r + mi * 16) * 128 + ks * 32 + a_cb));
            ldsm_x4(qf[ks][mi], sb + FA_Q + off);
        }

    float o[2][8][4];
#pragma unroll
    for (int mi = 0; mi < 2; mi++)
#pragma unroll
        for (int nj = 0; nj < 8; nj++)
#pragma unroll
            for (int r = 0; r < 4; r++) o[mi][nj][r] = 0.f;
    float ls[4] = { 0.f, 0.f, 0.f, 0.f };

    const int g    = lane >> 3;
    const int b_r  = ((g >> 1) << 3) + (lane & 7);
    const int b_cb = (g & 1) << 4;
    const int vrow = ((lane >> 3) & 1) * 8 + (lane & 7);
    const int vcb  = ((lane >> 4) & 1) * 16;
    const int warpRowMax = qt * 128 + wid * 32 + 31;   // last row this warp owns

    for (int kt = 0; kt < nkt; kt++) {
        if (kt + 1 < nkt) cp_wait<1>(); else cp_wait<0>();
        __syncthreads();
        if (kt + 2 < nkt) issue_kv(kt + 2, (kt + 2) % 3);

        // Fully-masked tile for this warp? (all keys above the diagonal)
        if (kt * 64 > warpRowMax) continue;

        const uint32_t kv = sb + FA_ST(kt % 3);

        // ---- S = Q K^T (fp16 single), K frags shared across both Q frags ----
        float s[2][8][4];
#pragma unroll
        for (int mi = 0; mi < 2; mi++)
#pragma unroll
            for (int nj = 0; nj < 8; nj++)
#pragma unroll
                for (int r = 0; r < 4; r++) s[mi][nj][r] = 0.f;

#pragma unroll
        for (int ks = 0; ks < 4; ks++) {
            uint32_t kb[4][4];
#pragma unroll
            for (int nt = 0; nt < 4; nt++) {
                uint32_t off = swz((uint32_t)((b_r + nt * 16) * 128 + ks * 32 + b_cb));
                ldsm_x4(kb[nt], kv + FA_K + off);
            }
#pragma unroll
            for (int mi = 0; mi < 2; mi++)
#pragma unroll
                for (int nj = 0; nj < 8; nj++) {
                    const uint32_t* bj = &kb[nj >> 1][(nj & 1) * 2];
                    mma16816h(s[mi][nj], qf[ks][mi], bj[0], bj[1]);
                }
        }

        // ---- causal mask (diagonal tiles only) ----
        if (kt * 64 + 63 > qt * 128 + wid * 32) {
            const int colb = kt * 64 + (lane & 3) * 2;
#pragma unroll
            for (int mi = 0; mi < 2; mi++) {
                const int r0 = qt * 128 + wid * 32 + mi * 16 + (lane >> 2);
                const int r1 = r0 + 8;
#pragma unroll
                for (int nj = 0; nj < 8; nj++) {
                    const int c0 = colb + nj * 8, c1 = c0 + 1;
                    if (c0 > r0) s[mi][nj][0] = -1e30f;
                    if (c1 > r0) s[mi][nj][1] = -1e30f;
                    if (c0 > r1) s[mi][nj][2] = -1e30f;
                    if (c1 > r1) s[mi][nj][3] = -1e30f;
                }
            }
        }

        // ---- p = 2^s (no max), accumulate l, pack P fp16 ----
        uint32_t ph[2][4][4];
#pragma unroll
        for (int mi = 0; mi < 2; mi++) {
#pragma unroll
            for (int nj = 0; nj < 8; nj++) {
                float p0 = ex2(s[mi][nj][0]);
                float p1 = ex2(s[mi][nj][1]);
                float p2 = ex2(s[mi][nj][2]);
                float p3 = ex2(s[mi][nj][3]);
                s[mi][nj][0] = p0; s[mi][nj][1] = p1;
                s[mi][nj][2] = p2; s[mi][nj][3] = p3;
                ls[mi * 2 + 0] += p0 + p1;
                ls[mi * 2 + 1] += p2 + p3;
            }
#pragma unroll
            for (int ks = 0; ks < 4; ks++) {
#pragma unroll
                for (int rr = 0; rr < 4; rr++) {
                    const int nj = 2 * ks + (rr >> 1);
                    const int r0 = (rr & 1) * 2;
                    __half2 hh = __floats2half2_rn(s[mi][nj][r0], s[mi][nj][r0 + 1]);
                    ph[mi][ks][rr] = *(uint32_t*)&hh;
                }
            }
        }

        // ---- O += P V (fp16), V frags shared across both row-halves ----
#pragma unroll
        for (int ks = 0; ks < 4; ks++) {
#pragma unroll
            for (int nd = 0; nd < 4; nd++) {
                uint32_t vf[4];
                uint32_t off = swz((uint32_t)((ks * 16 + vrow) * 128 + nd * 32 + vcb));
                ldsm_x4_t(vf, kv + FA_V + off);
#pragma unroll
                for (int mi = 0; mi < 2; mi++) {
                    mma16816h(o[mi][nd * 2],     ph[mi][ks], vf[0], vf[1]);
                    mma16816h(o[mi][nd * 2 + 1], ph[mi][ks], vf[2], vf[3]);
                }
            }
        }
    }

    // ---- epilogue: reduce l across quad lanes, O / l -> fp16 att ----
    float inv[4];
#pragma unroll
    for (int si = 0; si < 4; si++) {
        float l = ls[si];
        l += __shfl_xor_sync(0xffffffffu, l, 1);
        l += __shfl_xor_sync(0xffffffffu, l, 2);
        inv[si] = 1.f / l;
    }
    const int ecb = h * 64 + (lane & 3) * 2;
#pragma unroll
    for (int mi = 0; mi < 2; mi++) {
        const int er0 = qt * 128 + wid * 32 + mi * 16 + (lane >> 2);
        const size_t row = (size_t)b * T_ + er0;
#pragma unroll
        for (int nj = 0; nj < 8; nj++) {
            *(__half2*)(att + row * C_ + ecb + nj * 8) =
                __floats2half2_rn(o[mi][nj][0] * inv[mi * 2],
                                  o[mi][nj][1] * inv[mi * 2]);
            *(__half2*)(att + (row + 8) * C_ + ecb + nj * 8) =
                __floats2half2_rn(o[mi][nj][2] * inv[mi * 2 + 1],
                                  o[mi][nj][3] * inv[mi * 2 + 1]);
        }
    }
}

// ---------------------------------------------------------------------------
// Launch sequence: prepass -> QKV GEMM -> flash -> proj GEMM
// ---------------------------------------------------------------------------
extern "C" void kernel_launch(void* const* d_in, const int* in_sizes, int n_in,
                              void* d_out, int out_size)
{
    const float* x      = (const float*)d_in[0];
    const float* w_qkv  = (const float*)d_in[1];
    const float* b_qkv  = (const float*)d_in[2];
    const float* w_proj = (const float*)d_in[3];
    const float* b_proj = (const float*)d_in[4];
    float* out = (float*)d_out;

    __half *xh, *wt, *wt2, *qh, *kh, *vh;
    cudaGetSymbolAddress((void**)&xh, g_xh);
    cudaGetSymbolAddress((void**)&wt, g_wt);
    cudaGetSymbolAddress((void**)&wt2, g_wt2);
    cudaGetSymbolAddress((void**)&qh, g_qh);
    cudaGetSymbolAddress((void**)&kh, g_kh);
    cudaGetSymbolAddress((void**)&vh, g_vh);

    cudaFuncSetAttribute(gemm_qkv, cudaFuncAttributeMaxDynamicSharedMemorySize, SM_TOTAL);
    cudaFuncSetAttribute(gemm_proj, cudaFuncAttributeMaxDynamicSharedMemorySize, PJ_TOTAL);
    cudaFuncSetAttribute(flash_attn, cudaFuncAttributeMaxDynamicSharedMemorySize, FA_TOTAL);

    // 1) fused prepass: x->fp16, w_qkv->W^T fp16, w_proj->W^T fp16
    prepass<<<PRE_TOTAL, 256>>>(x, w_qkv, w_proj, xh, wt, wt2);

    // 2) QKV GEMM -> per-head q (scaled)/k/v fp16
    {
        dim3 grid(N_QKV / 128, M_ROWS / 128);
        gemm_qkv<<<grid, 256, SM_TOTAL>>>(xh, wt, b_qkv, qh, kh, vh,
                                          M_ROWS, N_QKV, C_);
    }
    // 3) flash attention -> fp16 att (reuses xh)
    {
        dim3 grid(T_ / 128, H_, B_);
        flash_attn<<<grid, 128, FA_TOTAL>>>(qh, kh, vh, xh);
    }
    // 4) proj GEMM -> fp32 out (128x64 tiles, 3 CTAs/SM)
    {
        dim3 grid(C_ / 64, M_ROWS / 128);
        gemm_proj<<<grid, 128, PJ_TOTAL>>>(xh, wt2, b_proj, out,
                                           M_ROWS, C_, C_);
    }
}

// round 16
// speedup vs baseline: 1.0064x; 1.0064x over previous
#include <cuda_runtime.h>
#include <cuda_bf16.h>
#include <cuda_fp16.h>
#include <cstdint>

// ---------------------------------------------------------------------------
// Problem constants
// ---------------------------------------------------------------------------
#define B_ 2
#define T_ 2048
#define C_ 1024
#define H_ 16
#define D_ 64
#define M_ROWS (B_ * T_)     // 4096
#define N_QKV  (3 * C_)      // 3072

// softmax scale * log2(e) folded into Q: (1/8) * 1.4426950408889634
#define QS 0.18033688011112042f

// Scratch (__device__ globals; allocation-free rule)
__device__ __half g_xh[(size_t)M_ROWS * C_];        // activations fp16 (x, then att)
__device__ __half g_wt[(size_t)N_QKV * C_];         // W_qkv^T fp16 [N,K]
__device__ __half g_wt2[(size_t)C_ * C_];           // W_proj^T fp16 [N,K]
// per-head fp16 [B,H,T,D]
__device__ __half g_qh[(size_t)B_ * H_ * T_ * D_];  // q (pre-scaled by QS)
__device__ __half g_kh[(size_t)B_ * H_ * T_ * D_];
__device__ __half g_vh[(size_t)B_ * H_ * T_ * D_];

// ---------------------------------------------------------------------------
// Warp MMA / async-copy helpers (sm_80+ baseline)
// ---------------------------------------------------------------------------
__device__ __forceinline__ uint32_t smem_to_u32(const void* p) {
    uint32_t a;
    asm("{ .reg .u64 t; cvta.to.shared.u64 t, %1; cvt.u32.u64 %0, t; }"
        : "=r"(a) : "l"(p));
    return a;
}
__device__ __forceinline__ void ldsm_x4(uint32_t (&r)[4], uint32_t addr) {
    asm volatile("ldmatrix.sync.aligned.m8n8.x4.shared.b16 {%0,%1,%2,%3}, [%4];"
                 : "=r"(r[0]), "=r"(r[1]), "=r"(r[2]), "=r"(r[3]) : "r"(addr));
}
__device__ __forceinline__ void ldsm_x4_t(uint32_t (&r)[4], uint32_t addr) {
    asm volatile("ldmatrix.sync.aligned.m8n8.x4.trans.shared.b16 {%0,%1,%2,%3}, [%4];"
                 : "=r"(r[0]), "=r"(r[1]), "=r"(r[2]), "=r"(r[3]) : "r"(addr));
}
__device__ __forceinline__ void mma16816h(float (&d)[4],
                                          const uint32_t (&a)[4],
                                          const uint32_t b0, const uint32_t b1) {
    asm volatile(
        "mma.sync.aligned.m16n8k16.row.col.f32.f16.f16.f32 "
        "{%0,%1,%2,%3}, {%4,%5,%6,%7}, {%8,%9}, {%0,%1,%2,%3};"
        : "+f"(d[0]), "+f"(d[1]), "+f"(d[2]), "+f"(d[3])
        : "r"(a[0]), "r"(a[1]), "r"(a[2]), "r"(a[3]), "r"(b0), "r"(b1));
}
__device__ __forceinline__ uint32_t swz(uint32_t off) {
    return off ^ ((off >> 3) & 0x70);
}
__device__ __forceinline__ float ex2(float x) {
    float y; asm("ex2.approx.ftz.f32 %0, %1;" : "=f"(y) : "f"(x)); return y;
}
__device__ __forceinline__ void cp16(uint32_t dst, const void* src) {
    asm volatile("cp.async.ca.shared.global [%0], [%1], 16;" :: "r"(dst), "l"(src));
}
__device__ __forceinline__ void cp_commit() {
    asm volatile("cp.async.commit_group;" ::: "memory");
}
template<int N> __device__ __forceinline__ void cp_wait() {
    asm volatile("cp.async.wait_group %0;" :: "n"(N) : "memory");
}

// ---------------------------------------------------------------------------
// Fused prepass (R13): x->fp16, w_qkv->W^T, w_proj->W^T in one kernel.
// ---------------------------------------------------------------------------
#define PRE_XBLOCKS   4096
#define PRE_QKVBLOCKS 3072
#define PRE_PROJBLOCKS 1024
#define PRE_TOTAL (PRE_XBLOCKS + PRE_QKVBLOCKS + PRE_PROJBLOCKS)

__global__ __launch_bounds__(256)
void prepass(const float* __restrict__ x,
             const float* __restrict__ w_qkv, const float* __restrict__ w_proj,
             __half* __restrict__ xh,
             __half* __restrict__ wt_qkv, __half* __restrict__ wt_proj)
{
    const int bid = blockIdx.x;

    if (bid < PRE_XBLOCKS) {
        int i = bid * 256 + threadIdx.x;
        float4 v = ((const float4*)x)[i];
        ((__half2*)xh)[i * 2 + 0] = __floats2half2_rn(v.x, v.y);
        ((__half2*)xh)[i * 2 + 1] = __floats2half2_rn(v.z, v.w);
        return;
    }

    const float* W;
    __half* Wt;
    int N, tileIdx;
    if (bid < PRE_XBLOCKS + PRE_QKVBLOCKS) {
        W = w_qkv; Wt = wt_qkv; N = N_QKV;
        tileIdx = bid - PRE_XBLOCKS;
    } else {
        W = w_proj; Wt = wt_proj; N = C_;
        tileIdx = bid - PRE_XBLOCKS - PRE_QKVBLOCKS;
    }
    const int ntilesN = N / 32;
    const int n0 = (tileIdx % ntilesN) * 32;
    const int k0 = (tileIdx / ntilesN) * 32;

    __shared__ float tile[32][33];
    const int tx = threadIdx.x & 31;
    const int ty = threadIdx.x >> 5;
#pragma unroll
    for (int r = ty; r < 32; r += 8)
        tile[r][tx] = W[(size_t)(k0 + r) * N + n0 + tx];
    __syncthreads();
#pragma unroll
    for (int r = ty; r < 32; r += 8)
        Wt[(size_t)(n0 + r) * C_ + k0 + tx] = __float2half_rn(tile[tx][r]);
}

// ---------------------------------------------------------------------------
// HMMA GEMM fp16 single-term, 256 threads / 8 warps, warp tile 64x32,
// __launch_bounds__(256, 2) -> 128 regs, 2 CTAs/SM.  (R14 known-good)
// MODE 0: fp32 C + bias.  MODE 1: per-head q(scaled)/k/v scatter.
// ---------------------------------------------------------------------------
#define SM_A  0
#define SM_B  16384
#define SM_STAGE 32768
#define SM_TOTAL (3 * SM_STAGE)     // 98304

template<int MODE>
__global__ __launch_bounds__(256, 2)
void gemm_f16(const __half* __restrict__ A, const __half* __restrict__ Bt,
              const float* __restrict__ bias, float* __restrict__ Cout,
              __half* __restrict__ qh, __half* __restrict__ kh,
              __half* __restrict__ vh,
              int M, int N, int K)
{
    extern __shared__ char smem[];
    const uint32_t sb = smem_to_u32(smem);

    const int tid  = threadIdx.x;
    const int wid  = tid >> 5;
    const int lane = tid & 31;
    const int rowBase = blockIdx.y * 128;
    const int colBase = blockIdx.x * 128;

    const int warp_m = wid & 1;        // 2 x 64-row halves
    const int warp_n = wid >> 1;       // 4 x 32-col quarters

    float acc[4][4][4];
#pragma unroll
    for (int i = 0; i < 4; i++)
#pragma unroll
        for (int j = 0; j < 4; j++)
#pragma unroll
            for (int r = 0; r < 4; r++) acc[i][j][r] = 0.f;

    const int a_r  = warp_m * 64 + (lane & 15);
    const int a_cb = (lane >> 4) << 4;
    const int g    = lane >> 3;
    const int b_r  = warp_n * 32 + ((g >> 1) << 3) + (lane & 7);
    const int b_cb = (g & 1) << 4;

    int ld_r[4], ld_cb[4];
    uint32_t ld_sw[4];
#pragma unroll
    for (int it = 0; it < 4; it++) {
        int idx = it * 256 + tid;
        ld_r[it]  = idx >> 3;
        ld_cb[it] = (idx & 7) << 4;
        ld_sw[it] = swz((uint32_t)(ld_r[it] * 128 + ld_cb[it]));
    }

    auto issue = [&](int ch, int st) {
        const int k0 = ch * 64;
        const uint32_t sbase = sb + st * SM_STAGE;
#pragma unroll
        for (int it = 0; it < 4; it++) {
            const int r = ld_r[it], cb = ld_cb[it];
            const uint32_t sw = ld_sw[it];
            cp16(sbase + SM_A + sw, (const char*)(A  + (size_t)(rowBase + r) * K + k0) + cb);
            cp16(sbase + SM_B + sw, (const char*)(Bt + (size_t)(colBase + r) * K + k0) + cb);
        }
        cp_commit();
    };

    const int nChunks = K / 64;
    issue(0, 0);
    issue(1, 1);

    for (int ch = 0; ch < nChunks; ch++) {
        if (ch + 1 < nChunks) cp_wait<1>(); else cp_wait<0>();
        __syncthreads();
        if (ch + 2 < nChunks) issue(ch + 2, (ch + 2) % 3);

        const uint32_t sbase = sb + (ch % 3) * SM_STAGE;
#pragma unroll
        for (int ks = 0; ks < 4; ks++) {
            const int kb = ks * 32;
            uint32_t af[4][4];
#pragma unroll
            for (int mi = 0; mi < 4; mi++) {
                uint32_t off = swz((uint32_t)((a_r + mi * 16) * 128 + kb + a_cb));
                ldsm_x4(af[mi], sbase + SM_A + off);
            }
            uint32_t bf[2][4];
#pragma unroll
            for (int nt = 0; nt < 2; nt++) {
                uint32_t off = swz((uint32_t)((b_r + nt * 16) * 128 + kb + b_cb));
                ldsm_x4(bf[nt], sbase + SM_B + off);
            }
#pragma unroll
            for (int mi = 0; mi < 4; mi++)
#pragma unroll
                for (int nj = 0; nj < 4; nj++) {
                    const uint32_t* bj = &bf[nj >> 1][(nj & 1) * 2];
                    mma16816h(acc[mi][nj], af[mi], bj[0], bj[1]);
                }
        }
    }

    const int er = rowBase + warp_m * 64 + (lane >> 2);
    const int ec = colBase + warp_n * 32 + (lane & 3) * 2;

    if (MODE == 0) {
#pragma unroll
        for (int mi = 0; mi < 4; mi++) {
#pragma unroll
            for (int nj = 0; nj < 4; nj++) {
                const int c = ec + nj * 8;
                const float bx = __ldg(bias + c);
                const float by = __ldg(bias + c + 1);
                float2 v0 = { acc[mi][nj][0] + bx, acc[mi][nj][1] + by };
                float2 v1 = { acc[mi][nj][2] + bx, acc[mi][nj][3] + by };
                *(float2*)(Cout + (size_t)(er + mi * 16) * N + c) = v0;
                *(float2*)(Cout + (size_t)(er + mi * 16 + 8) * N + c) = v1;
            }
        }
    } else {
#pragma unroll
        for (int nj = 0; nj < 4; nj++) {
            const int c   = ec + nj * 8;
            const int sec = c >> 10;             // 0=q,1=k,2=v
            const int hh  = (c & 1023) >> 6;
            const int dd  = c & 63;
            const float sc = (sec == 0) ? QS : 1.f;
            const float bx = __ldg(bias + c)     * sc;
            const float by = __ldg(bias + c + 1) * sc;
            __half* dp = (sec == 0) ? qh : (sec == 1) ? kh : vh;
#pragma unroll
            for (int mi = 0; mi < 4; mi++) {
#pragma unroll
                for (int half = 0; half < 2; half++) {
                    const int r = er + mi * 16 + half * 8;
                    const int bb = r >> 11, tt = r & 2047;
                    const size_t dst = (((size_t)bb * H_ + hh) * T_ + tt) * D_ + dd;
                    float v0 = fmaf(acc[mi][nj][half * 2],     sc, bx);
                    float v1 = fmaf(acc[mi][nj][half * 2 + 1], sc, by);
                    *(__half2*)(dp + dst) = __floats2half2_rn(v0, v1);
                }
            }
        }
    }
}

// ---------------------------------------------------------------------------
// Flash attention: fp16 single-term, m=0 softmax, 128 threads / 4 warps,
// 32 q-rows per warp, Q frags hoisted, per-warp masked-tile skip,
// 64-key tiles, cp.async 4-STAGE pipeline (3 tiles in flight).
// smem = 16 + 4*16 = 80KB -> 2 CTAs/SM (160KB).
// ---------------------------------------------------------------------------
#define FA_Q 0
#define FA_STAGE0 16384
#define FA_STSZ 16384
#define FA_ST(s) (FA_STAGE0 + (s) * FA_STSZ)
#define FA_K 0
#define FA_V 8192
#define FA_TOTAL (FA_STAGE0 + 4 * FA_STSZ)   // 81920

__global__ __launch_bounds__(128)
void flash_attn(const __half* __restrict__ qh, const __half* __restrict__ kh,
                const __half* __restrict__ vh, __half* __restrict__ att)
{
    extern __shared__ char smem[];
    const uint32_t sb = smem_to_u32(smem);
    const int tid = threadIdx.x, wid = tid >> 5, lane = tid & 31;
    const int h = blockIdx.y, b = blockIdx.z;
    const int qt = gridDim.x - 1 - blockIdx.x;    // big tiles first

    const size_t hoff = ((size_t)b * H_ + h) * T_ * D_;
    const char* qh_p = (const char*)(qh + hoff + (size_t)qt * 128 * D_);
    const char* kh_p = (const char*)(kh + hoff);
    const char* vh_p = (const char*)(vh + hoff);

    auto issue_kv = [&](int kt, int st) {
        const uint32_t sbase = sb + FA_ST(st);
#pragma unroll
        for (int it = 0; it < 4; it++) {
            int idx = it * 128 + tid;            // 0..511
            int r = idx >> 3, cb = (idx & 7) << 4;
            uint32_t sw = swz((uint32_t)(r * 128 + cb));
            size_t go = (size_t)(kt * 64 + r) * 128 + cb;    // bytes
            cp16(sbase + FA_K + sw, kh_p + go);
            cp16(sbase + FA_V + sw, vh_p + go);
        }
        cp_commit();
    };

    const int nkt = 2 * qt + 2;
    issue_kv(0, 0);
    issue_kv(1, 1);
    issue_kv(2 < nkt ? 2 : 0, 2);   // third prefetch (harmless refill if nkt<3)

    // Load Q tile into smem (plain stores), then hoist Q frags to registers.
#pragma unroll
    for (int it = 0; it < 8; it++) {
        int idx = it * 128 + tid;
        int r = idx >> 3, cb = (idx & 7) << 4;
        uint32_t sw = swz((uint32_t)(r * 128 + cb));
        *(uint4*)(smem + FA_Q + sw) = *(const uint4*)(qh_p + r * 128 + cb);
    }
    __syncthreads();

    const int a_r  = wid * 32 + (lane & 15);
    const int a_cb = (lane >> 4) << 4;
    uint32_t qf[4][2][4];                 // [ks][mi][reg], loop-invariant
#pragma unroll
    for (int ks = 0; ks < 4; ks++)
#pragma unroll
        for (int mi = 0; mi < 2; mi++) {
            uint32_t off = swz((uint32_t)((a_r + mi * 16) * 128 + ks * 32 + a_cb));
            ldsm_x4(qf[ks][mi], sb + FA_Q + off);
        }

    float o[2][8][4];
#pragma unroll
    for (int mi = 0; mi < 2; mi++)
#pragma unroll
        for (int nj = 0; nj < 8; nj++)
#pragma unroll
            for (int r = 0; r < 4; r++) o[mi][nj][r] = 0.f;
    float ls[4] = { 0.f, 0.f, 0.f, 0.f };

    const int g    = lane >> 3;
    const int b_r  = ((g >> 1) << 3) + (lane & 7);
    const int b_cb = (g & 1) << 4;
    const int vrow = ((lane >> 3) & 1) * 8 + (lane & 7);
    const int vcb  = ((lane >> 4) & 1) * 16;
    const int warpRowMax = qt * 128 + wid * 32 + 31;   // last row this warp owns

    for (int kt = 0; kt < nkt; kt++) {
        // groups outstanding: up to kt+2 issued; wait until group kt done.
        if (kt + 2 < nkt)      cp_wait<2>();
        else if (kt + 1 < nkt) cp_wait<1>();
        else                   cp_wait<0>();
        __syncthreads();
        if (kt + 3 < nkt) issue_kv(kt + 3, (kt + 3) & 3);

        // Fully-masked tile for this warp? (all keys above the diagonal)
        if (kt * 64 > warpRowMax) continue;

        const uint32_t kv = sb + FA_ST(kt & 3);

        // ---- S = Q K^T (fp16 single), K frags shared across both Q frags ----
        float s[2][8][4];
#pragma unroll
        for (int mi = 0; mi < 2; mi++)
#pragma unroll
            for (int nj = 0; nj < 8; nj++)
#pragma unroll
                for (int r = 0; r < 4; r++) s[mi][nj][r] = 0.f;

#pragma unroll
        for (int ks = 0; ks < 4; ks++) {
            uint32_t kb[4][4];
#pragma unroll
            for (int nt = 0; nt < 4; nt++) {
                uint32_t off = swz((uint32_t)((b_r + nt * 16) * 128 + ks * 32 + b_cb));
                ldsm_x4(kb[nt], kv + FA_K + off);
            }
#pragma unroll
            for (int mi = 0; mi < 2; mi++)
#pragma unroll
                for (int nj = 0; nj < 8; nj++) {
                    const uint32_t* bj = &kb[nj >> 1][(nj & 1) * 2];
                    mma16816h(s[mi][nj], qf[ks][mi], bj[0], bj[1]);
                }
        }

        // ---- causal mask (diagonal tiles only) ----
        if (kt * 64 + 63 > qt * 128 + wid * 32) {
            const int colb = kt * 64 + (lane & 3) * 2;
#pragma unroll
            for (int mi = 0; mi < 2; mi++) {
                const int r0 = qt * 128 + wid * 32 + mi * 16 + (lane >> 2);
                const int r1 = r0 + 8;
#pragma unroll
                for (int nj = 0; nj < 8; nj++) {
                    const int c0 = colb + nj * 8, c1 = c0 + 1;
                    if (c0 > r0) s[mi][nj][0] = -1e30f;
                    if (c1 > r0) s[mi][nj][1] = -1e30f;
                    if (c0 > r1) s[mi][nj][2] = -1e30f;
                    if (c1 > r1) s[mi][nj][3] = -1e30f;
                }
            }
        }

        // ---- p = 2^s (no max), accumulate l, pack P fp16 ----
        uint32_t ph[2][4][4];
#pragma unroll
        for (int mi = 0; mi < 2; mi++) {
#pragma unroll
            for (int nj = 0; nj < 8; nj++) {
                float p0 = ex2(s[mi][nj][0]);
                float p1 = ex2(s[mi][nj][1]);
                float p2 = ex2(s[mi][nj][2]);
                float p3 = ex2(s[mi][nj][3]);
                s[mi][nj][0] = p0; s[mi][nj][1] = p1;
                s[mi][nj][2] = p2; s[mi][nj][3] = p3;
                ls[mi * 2 + 0] += p0 + p1;
                ls[mi * 2 + 1] += p2 + p3;
            }
#pragma unroll
            for (int ks = 0; ks < 4; ks++) {
#pragma unroll
                for (int rr = 0; rr < 4; rr++) {
                    const int nj = 2 * ks + (rr >> 1);
                    const int r0 = (rr & 1) * 2;
                    __half2 hh = __floats2half2_rn(s[mi][nj][r0], s[mi][nj][r0 + 1]);
                    ph[mi][ks][rr] = *(uint32_t*)&hh;
                }
            }
        }

        // ---- O += P V (fp16), V frags shared across both row-halves ----
#pragma unroll
        for (int ks = 0; ks < 4; ks++) {
#pragma unroll
            for (int nd = 0; nd < 4; nd++) {
                uint32_t vf[4];
                uint32_t off = swz((uint32_t)((ks * 16 + vrow) * 128 + nd * 32 + vcb));
                ldsm_x4_t(vf, kv + FA_V + off);
#pragma unroll
                for (int mi = 0; mi < 2; mi++) {
                    mma16816h(o[mi][nd * 2],     ph[mi][ks], vf[0], vf[1]);
                    mma16816h(o[mi][nd * 2 + 1], ph[mi][ks], vf[2], vf[3]);
                }
            }
        }
    }

    // ---- epilogue: reduce l across quad lanes, O / l -> fp16 att ----
    float inv[4];
#pragma unroll
    for (int si = 0; si < 4; si++) {
        float l = ls[si];
        l += __shfl_xor_sync(0xffffffffu, l, 1);
        l += __shfl_xor_sync(0xffffffffu, l, 2);
        inv[si] = 1.f / l;
    }
    const int ecb = h * 64 + (lane & 3) * 2;
#pragma unroll
    for (int mi = 0; mi < 2; mi++) {
        const int er0 = qt * 128 + wid * 32 + mi * 16 + (lane >> 2);
        const size_t row = (size_t)b * T_ + er0;
#pragma unroll
        for (int nj = 0; nj < 8; nj++) {
            *(__half2*)(att + row * C_ + ecb + nj * 8) =
                __floats2half2_rn(o[mi][nj][0] * inv[mi * 2],
                                  o[mi][nj][1] * inv[mi * 2]);
            *(__half2*)(att + (row + 8) * C_ + ecb + nj * 8) =
                __floats2half2_rn(o[mi][nj][2] * inv[mi * 2 + 1],
                                  o[mi][nj][3] * inv[mi * 2 + 1]);
        }
    }
}

// ---------------------------------------------------------------------------
// Launch sequence: prepass -> QKV GEMM -> flash -> proj GEMM
// ---------------------------------------------------------------------------
extern "C" void kernel_launch(void* const* d_in, const int* in_sizes, int n_in,
                              void* d_out, int out_size)
{
    const float* x      = (const float*)d_in[0];
    const float* w_qkv  = (const float*)d_in[1];
    const float* b_qkv  = (const float*)d_in[2];
    const float* w_proj = (const float*)d_in[3];
    const float* b_proj = (const float*)d_in[4];
    float* out = (float*)d_out;

    __half *xh, *wt, *wt2, *qh, *kh, *vh;
    cudaGetSymbolAddress((void**)&xh, g_xh);
    cudaGetSymbolAddress((void**)&wt, g_wt);
    cudaGetSymbolAddress((void**)&wt2, g_wt2);
    cudaGetSymbolAddress((void**)&qh, g_qh);
    cudaGetSymbolAddress((void**)&kh, g_kh);
    cudaGetSymbolAddress((void**)&vh, g_vh);

    cudaFuncSetAttribute(gemm_f16<0>, cudaFuncAttributeMaxDynamicSharedMemorySize, SM_TOTAL);
    cudaFuncSetAttribute(gemm_f16<1>, cudaFuncAttributeMaxDynamicSharedMemorySize, SM_TOTAL);
    cudaFuncSetAttribute(flash_attn, cudaFuncAttributeMaxDynamicSharedMemorySize, FA_TOTAL);

    // 1) fused prepass: x->fp16, w_qkv->W^T fp16, w_proj->W^T fp16
    prepass<<<PRE_TOTAL, 256>>>(x, w_qkv, w_proj, xh, wt, wt2);

    // 2) QKV GEMM -> per-head q (scaled)/k/v fp16
    {
        dim3 grid(N_QKV / 128, M_ROWS / 128);
        gemm_f16<1><<<grid, 256, SM_TOTAL>>>(xh, wt, b_qkv, nullptr,
                                             qh, kh, vh, M_ROWS, N_QKV, C_);
    }
    // 3) flash attention -> fp16 att (reuses xh)
    {
        dim3 grid(T_ / 128, H_, B_);
        flash_attn<<<grid, 128, FA_TOTAL>>>(qh, kh, vh, xh);
    }
    // 4) proj GEMM -> fp32 out (R14 config)
    {
        dim3 grid(C_ / 128, M_ROWS / 128);
        gemm_f16<0><<<grid, 256, SM_TOTAL>>>(xh, wt2, b_proj, out,
                                             nullptr, nullptr, nullptr,
                                             M_ROWS, C_, C_);
    }
}

// round 17
// speedup vs baseline: 1.0192x; 1.0127x over previous
#include <cuda_runtime.h>
#include <cuda_bf16.h>
#include <cuda_fp16.h>
#include <cstdint>

// ---------------------------------------------------------------------------
// Problem constants
// ---------------------------------------------------------------------------
#define B_ 2
#define T_ 2048
#define C_ 1024
#define H_ 16
#define D_ 64
#define M_ROWS (B_ * T_)     // 4096
#define N_QKV  (3 * C_)      // 3072

// softmax scale * log2(e) folded into Q: (1/8) * 1.4426950408889634
#define QS 0.18033688011112042f

// Scratch (__device__ globals; allocation-free rule)
__device__ __half g_xh[(size_t)M_ROWS * C_];        // activations fp16 (x, then att)
__device__ __half g_wt[(size_t)N_QKV * C_];         // W_qkv^T fp16 [N,K]
__device__ __half g_wt2[(size_t)C_ * C_];           // W_proj^T fp16 [N,K]
// per-head fp16 [B,H,T,D]
__device__ __half g_qh[(size_t)B_ * H_ * T_ * D_];  // q (pre-scaled by QS)
__device__ __half g_kh[(size_t)B_ * H_ * T_ * D_];
__device__ __half g_vh[(size_t)B_ * H_ * T_ * D_];

// ---------------------------------------------------------------------------
// Warp MMA / async-copy helpers (sm_80+ baseline)
// ---------------------------------------------------------------------------
__device__ __forceinline__ uint32_t smem_to_u32(const void* p) {
    uint32_t a;
    asm("{ .reg .u64 t; cvta.to.shared.u64 t, %1; cvt.u32.u64 %0, t; }"
        : "=r"(a) : "l"(p));
    return a;
}
__device__ __forceinline__ void ldsm_x4(uint32_t (&r)[4], uint32_t addr) {
    asm volatile("ldmatrix.sync.aligned.m8n8.x4.shared.b16 {%0,%1,%2,%3}, [%4];"
                 : "=r"(r[0]), "=r"(r[1]), "=r"(r[2]), "=r"(r[3]) : "r"(addr));
}
__device__ __forceinline__ void ldsm_x4_t(uint32_t (&r)[4], uint32_t addr) {
    asm volatile("ldmatrix.sync.aligned.m8n8.x4.trans.shared.b16 {%0,%1,%2,%3}, [%4];"
                 : "=r"(r[0]), "=r"(r[1]), "=r"(r[2]), "=r"(r[3]) : "r"(addr));
}
__device__ __forceinline__ void mma16816h(float (&d)[4],
                                          const uint32_t (&a)[4],
                                          const uint32_t b0, const uint32_t b1) {
    asm volatile(
        "mma.sync.aligned.m16n8k16.row.col.f32.f16.f16.f32 "
        "{%0,%1,%2,%3}, {%4,%5,%6,%7}, {%8,%9}, {%0,%1,%2,%3};"
        : "+f"(d[0]), "+f"(d[1]), "+f"(d[2]), "+f"(d[3])
        : "r"(a[0]), "r"(a[1]), "r"(a[2]), "r"(a[3]), "r"(b0), "r"(b1));
}
__device__ __forceinline__ uint32_t swz(uint32_t off) {
    return off ^ ((off >> 3) & 0x70);
}
__device__ __forceinline__ float ex2(float x) {
    float y; asm("ex2.approx.ftz.f32 %0, %1;" : "=f"(y) : "f"(x)); return y;
}
__device__ __forceinline__ void cp16(uint32_t dst, const void* src) {
    asm volatile("cp.async.ca.shared.global [%0], [%1], 16;" :: "r"(dst), "l"(src));
}
__device__ __forceinline__ void cp_commit() {
    asm volatile("cp.async.commit_group;" ::: "memory");
}
template<int N> __device__ __forceinline__ void cp_wait() {
    asm volatile("cp.async.wait_group %0;" :: "n"(N) : "memory");
}

// ---------------------------------------------------------------------------
// Fused prepass (R13): x->fp16, w_qkv->W^T, w_proj->W^T in one kernel.
// ---------------------------------------------------------------------------
#define PRE_XBLOCKS   4096
#define PRE_QKVBLOCKS 3072
#define PRE_PROJBLOCKS 1024
#define PRE_TOTAL (PRE_XBLOCKS + PRE_QKVBLOCKS + PRE_PROJBLOCKS)

__global__ __launch_bounds__(256)
void prepass(const float* __restrict__ x,
             const float* __restrict__ w_qkv, const float* __restrict__ w_proj,
             __half* __restrict__ xh,
             __half* __restrict__ wt_qkv, __half* __restrict__ wt_proj)
{
    const int bid = blockIdx.x;

    if (bid < PRE_XBLOCKS) {
        int i = bid * 256 + threadIdx.x;
        float4 v = ((const float4*)x)[i];
        ((__half2*)xh)[i * 2 + 0] = __floats2half2_rn(v.x, v.y);
        ((__half2*)xh)[i * 2 + 1] = __floats2half2_rn(v.z, v.w);
        return;
    }

    const float* W;
    __half* Wt;
    int N, tileIdx;
    if (bid < PRE_XBLOCKS + PRE_QKVBLOCKS) {
        W = w_qkv; Wt = wt_qkv; N = N_QKV;
        tileIdx = bid - PRE_XBLOCKS;
    } else {
        W = w_proj; Wt = wt_proj; N = C_;
        tileIdx = bid - PRE_XBLOCKS - PRE_QKVBLOCKS;
    }
    const int ntilesN = N / 32;
    const int n0 = (tileIdx % ntilesN) * 32;
    const int k0 = (tileIdx / ntilesN) * 32;

    __shared__ float tile[32][33];
    const int tx = threadIdx.x & 31;
    const int ty = threadIdx.x >> 5;
#pragma unroll
    for (int r = ty; r < 32; r += 8)
        tile[r][tx] = W[(size_t)(k0 + r) * N + n0 + tx];
    __syncthreads();
#pragma unroll
    for (int r = ty; r < 32; r += 8)
        Wt[(size_t)(n0 + r) * C_ + k0 + tx] = __float2half_rn(tile[tx][r]);
}

// ---------------------------------------------------------------------------
// HMMA GEMM fp16 single-term, 256 threads / 8 warps, warp tile 64x32,
// __launch_bounds__(256, 2) -> 128 regs, 2 CTAs/SM.  (R14 known-good)
// MODE 0: fp32 C + bias.  MODE 1: per-head q(scaled)/k/v scatter.
// ---------------------------------------------------------------------------
#define SM_A  0
#define SM_B  16384
#define SM_STAGE 32768
#define SM_TOTAL (3 * SM_STAGE)     // 98304

template<int MODE>
__global__ __launch_bounds__(256, 2)
void gemm_f16(const __half* __restrict__ A, const __half* __restrict__ Bt,
              const float* __restrict__ bias, float* __restrict__ Cout,
              __half* __restrict__ qh, __half* __restrict__ kh,
              __half* __restrict__ vh,
              int M, int N, int K)
{
    extern __shared__ char smem[];
    const uint32_t sb = smem_to_u32(smem);

    const int tid  = threadIdx.x;
    const int wid  = tid >> 5;
    const int lane = tid & 31;
    const int rowBase = blockIdx.y * 128;
    const int colBase = blockIdx.x * 128;

    const int warp_m = wid & 1;        // 2 x 64-row halves
    const int warp_n = wid >> 1;       // 4 x 32-col quarters

    float acc[4][4][4];
#pragma unroll
    for (int i = 0; i < 4; i++)
#pragma unroll
        for (int j = 0; j < 4; j++)
#pragma unroll
            for (int r = 0; r < 4; r++) acc[i][j][r] = 0.f;

    const int a_r  = warp_m * 64 + (lane & 15);
    const int a_cb = (lane >> 4) << 4;
    const int g    = lane >> 3;
    const int b_r  = warp_n * 32 + ((g >> 1) << 3) + (lane & 7);
    const int b_cb = (g & 1) << 4;

    int ld_r[4], ld_cb[4];
    uint32_t ld_sw[4];
#pragma unroll
    for (int it = 0; it < 4; it++) {
        int idx = it * 256 + tid;
        ld_r[it]  = idx >> 3;
        ld_cb[it] = (idx & 7) << 4;
        ld_sw[it] = swz((uint32_t)(ld_r[it] * 128 + ld_cb[it]));
    }

    auto issue = [&](int ch, int st) {
        const int k0 = ch * 64;
        const uint32_t sbase = sb + st * SM_STAGE;
#pragma unroll
        for (int it = 0; it < 4; it++) {
            const int r = ld_r[it], cb = ld_cb[it];
            const uint32_t sw = ld_sw[it];
            cp16(sbase + SM_A + sw, (const char*)(A  + (size_t)(rowBase + r) * K + k0) + cb);
            cp16(sbase + SM_B + sw, (const char*)(Bt + (size_t)(colBase + r) * K + k0) + cb);
        }
        cp_commit();
    };

    const int nChunks = K / 64;
    issue(0, 0);
    issue(1, 1);

    for (int ch = 0; ch < nChunks; ch++) {
        if (ch + 1 < nChunks) cp_wait<1>(); else cp_wait<0>();
        __syncthreads();
        if (ch + 2 < nChunks) issue(ch + 2, (ch + 2) % 3);

        const uint32_t sbase = sb + (ch % 3) * SM_STAGE;
#pragma unroll
        for (int ks = 0; ks < 4; ks++) {
            const int kb = ks * 32;
            uint32_t af[4][4];
#pragma unroll
            for (int mi = 0; mi < 4; mi++) {
                uint32_t off = swz((uint32_t)((a_r + mi * 16) * 128 + kb + a_cb));
                ldsm_x4(af[mi], sbase + SM_A + off);
            }
            uint32_t bf[2][4];
#pragma unroll
            for (int nt = 0; nt < 2; nt++) {
                uint32_t off = swz((uint32_t)((b_r + nt * 16) * 128 + kb + b_cb));
                ldsm_x4(bf[nt], sbase + SM_B + off);
            }
#pragma unroll
            for (int mi = 0; mi < 4; mi++)
#pragma unroll
                for (int nj = 0; nj < 4; nj++) {
                    const uint32_t* bj = &bf[nj >> 1][(nj & 1) * 2];
                    mma16816h(acc[mi][nj], af[mi], bj[0], bj[1]);
                }
        }
    }

    const int er = rowBase + warp_m * 64 + (lane >> 2);
    const int ec = colBase + warp_n * 32 + (lane & 3) * 2;

    if (MODE == 0) {
#pragma unroll
        for (int mi = 0; mi < 4; mi++) {
#pragma unroll
            for (int nj = 0; nj < 4; nj++) {
                const int c = ec + nj * 8;
                const float bx = __ldg(bias + c);
                const float by = __ldg(bias + c + 1);
                float2 v0 = { acc[mi][nj][0] + bx, acc[mi][nj][1] + by };
                float2 v1 = { acc[mi][nj][2] + bx, acc[mi][nj][3] + by };
                *(float2*)(Cout + (size_t)(er + mi * 16) * N + c) = v0;
                *(float2*)(Cout + (size_t)(er + mi * 16 + 8) * N + c) = v1;
            }
        }
    } else {
#pragma unroll
        for (int nj = 0; nj < 4; nj++) {
            const int c   = ec + nj * 8;
            const int sec = c >> 10;             // 0=q,1=k,2=v
            const int hh  = (c & 1023) >> 6;
            const int dd  = c & 63;
            const float sc = (sec == 0) ? QS : 1.f;
            const float bx = __ldg(bias + c)     * sc;
            const float by = __ldg(bias + c + 1) * sc;
            __half* dp = (sec == 0) ? qh : (sec == 1) ? kh : vh;
#pragma unroll
            for (int mi = 0; mi < 4; mi++) {
#pragma unroll
                for (int half = 0; half < 2; half++) {
                    const int r = er + mi * 16 + half * 8;
                    const int bb = r >> 11, tt = r & 2047;
                    const size_t dst = (((size_t)bb * H_ + hh) * T_ + tt) * D_ + dd;
                    float v0 = fmaf(acc[mi][nj][half * 2],     sc, bx);
                    float v1 = fmaf(acc[mi][nj][half * 2 + 1], sc, by);
                    *(__half2*)(dp + dst) = __floats2half2_rn(v0, v1);
                }
            }
        }
    }
}

// ---------------------------------------------------------------------------
// Flash attention v4: fp16 single-term, m=0 softmax, 128 threads / 4 warps,
// 32 q-rows per warp, Q frags hoisted. Each 64-key tile processed in TWO
// 32-key halves (S -> ex2/pack -> PV per half) to shrink live registers:
// __launch_bounds__(128, 3) -> 3 CTAs/SM (12 warps). 3-stage cp.async.
// Half-granular causal skip.
// ---------------------------------------------------------------------------
#define FA_Q 0
#define FA_STAGE0 16384
#define FA_STSZ 16384
#define FA_ST(s) (FA_STAGE0 + (s) * FA_STSZ)
#define FA_K 0
#define FA_V 8192
#define FA_TOTAL (FA_STAGE0 + 3 * FA_STSZ)   // 65536

__global__ __launch_bounds__(128, 3)
void flash_attn(const __half* __restrict__ qh, const __half* __restrict__ kh,
                const __half* __restrict__ vh, __half* __restrict__ att)
{
    extern __shared__ char smem[];
    const uint32_t sb = smem_to_u32(smem);
    const int tid = threadIdx.x, wid = tid >> 5, lane = tid & 31;
    const int h = blockIdx.y, b = blockIdx.z;
    const int qt = gridDim.x - 1 - blockIdx.x;    // big tiles first

    const size_t hoff = ((size_t)b * H_ + h) * T_ * D_;
    const char* qh_p = (const char*)(qh + hoff + (size_t)qt * 128 * D_);
    const char* kh_p = (const char*)(kh + hoff);
    const char* vh_p = (const char*)(vh + hoff);

    auto issue_kv = [&](int kt, int st) {
        const uint32_t sbase = sb + FA_ST(st);
#pragma unroll
        for (int it = 0; it < 4; it++) {
            int idx = it * 128 + tid;            // 0..511
            int r = idx >> 3, cb = (idx & 7) << 4;
            uint32_t sw = swz((uint32_t)(r * 128 + cb));
            size_t go = (size_t)(kt * 64 + r) * 128 + cb;    // bytes
            cp16(sbase + FA_K + sw, kh_p + go);
            cp16(sbase + FA_V + sw, vh_p + go);
        }
        cp_commit();
    };

    const int nkt = 2 * qt + 2;
    issue_kv(0, 0);
    issue_kv(1, 1);

    // Load Q tile into smem (plain stores), then hoist Q frags to registers.
#pragma unroll
    for (int it = 0; it < 8; it++) {
        int idx = it * 128 + tid;
        int r = idx >> 3, cb = (idx & 7) << 4;
        uint32_t sw = swz((uint32_t)(r * 128 + cb));
        *(uint4*)(smem + FA_Q + sw) = *(const uint4*)(qh_p + r * 128 + cb);
    }
    __syncthreads();

    const int a_r  = wid * 32 + (lane & 15);
    const int a_cb = (lane >> 4) << 4;
    uint32_t qf[4][2][4];                 // [ks][mi][reg], loop-invariant
#pragma unroll
    for (int ks = 0; ks < 4; ks++)
#pragma unroll
        for (int mi = 0; mi < 2; mi++) {
            uint32_t off = swz((uint32_t)((a_r + mi * 16) * 128 + ks * 32 + a_cb));
            ldsm_x4(qf[ks][mi], sb + FA_Q + off);
        }

    float o[2][8][4];
#pragma unroll
    for (int mi = 0; mi < 2; mi++)
#pragma unroll
        for (int nj = 0; nj < 8; nj++)
#pragma unroll
            for (int r = 0; r < 4; r++) o[mi][nj][r] = 0.f;
    float ls[4] = { 0.f, 0.f, 0.f, 0.f };

    const int g    = lane >> 3;
    const int b_r  = ((g >> 1) << 3) + (lane & 7);
    const int b_cb = (g & 1) << 4;
    const int vrow = ((lane >> 3) & 1) * 8 + (lane & 7);
    const int vcb  = ((lane >> 4) & 1) * 16;
    const int warpRow0   = qt * 128 + wid * 32;
    const int warpRowMax = warpRow0 + 31;

    for (int kt = 0; kt < nkt; kt++) {
        if (kt + 1 < nkt) cp_wait<1>(); else cp_wait<0>();
        __syncthreads();
        if (kt + 2 < nkt) issue_kv(kt + 2, (kt + 2) % 3);

        if (kt * 64 > warpRowMax) continue;   // fully-masked tile for this warp

        const uint32_t kv = sb + FA_ST(kt % 3);

        // Two 32-key halves: S -> ex2/pack -> PV each (smaller live set).
#pragma unroll
        for (int half = 0; half < 2; half++) {
            const int key0 = kt * 64 + half * 32;
            if (key0 > warpRowMax) continue;          // masked half

            const uint32_t koff = (uint32_t)(half * 32) * 128;

            // ---- S = Q K^T over 32 keys ----
            float s[2][4][4];
#pragma unroll
            for (int mi = 0; mi < 2; mi++)
#pragma unroll
                for (int nj = 0; nj < 4; nj++)
#pragma unroll
                    for (int r = 0; r < 4; r++) s[mi][nj][r] = 0.f;

#pragma unroll
            for (int ks = 0; ks < 4; ks++) {
                uint32_t kb[2][4];
#pragma unroll
                for (int nt = 0; nt < 2; nt++) {
                    uint32_t off = swz(koff +
                        (uint32_t)((b_r + nt * 16) * 128 + ks * 32 + b_cb));
                    ldsm_x4(kb[nt], kv + FA_K + off);
                }
#pragma unroll
                for (int mi = 0; mi < 2; mi++)
#pragma unroll
                    for (int nj = 0; nj < 4; nj++) {
                        const uint32_t* bj = &kb[nj >> 1][(nj & 1) * 2];
                        mma16816h(s[mi][nj], qf[ks][mi], bj[0], bj[1]);
                    }
            }

            // ---- causal mask (diagonal halves only) ----
            if (key0 + 31 > warpRow0) {
                const int colb = key0 + (lane & 3) * 2;
#pragma unroll
                for (int mi = 0; mi < 2; mi++) {
                    const int r0 = warpRow0 + mi * 16 + (lane >> 2);
                    const int r1 = r0 + 8;
#pragma unroll
                    for (int nj = 0; nj < 4; nj++) {
                        const int c0 = colb + nj * 8, c1 = c0 + 1;
                        if (c0 > r0) s[mi][nj][0] = -1e30f;
                        if (c1 > r0) s[mi][nj][1] = -1e30f;
                        if (c0 > r1) s[mi][nj][2] = -1e30f;
                        if (c1 > r1) s[mi][nj][3] = -1e30f;
                    }
                }
            }

            // ---- p = 2^s, accumulate l, pack P fp16 ----
            uint32_t ph[2][2][4];
#pragma unroll
            for (int mi = 0; mi < 2; mi++) {
#pragma unroll
                for (int nj = 0; nj < 4; nj++) {
                    float p0 = ex2(s[mi][nj][0]);
                    float p1 = ex2(s[mi][nj][1]);
                    float p2 = ex2(s[mi][nj][2]);
                    float p3 = ex2(s[mi][nj][3]);
                    s[mi][nj][0] = p0; s[mi][nj][1] = p1;
                    s[mi][nj][2] = p2; s[mi][nj][3] = p3;
                    ls[mi * 2 + 0] += p0 + p1;
                    ls[mi * 2 + 1] += p2 + p3;
                }
#pragma unroll
                for (int ks = 0; ks < 2; ks++) {
#pragma unroll
                    for (int rr = 0; rr < 4; rr++) {
                        const int nj = 2 * ks + (rr >> 1);
                        const int r0 = (rr & 1) * 2;
                        __half2 hh = __floats2half2_rn(s[mi][nj][r0], s[mi][nj][r0 + 1]);
                        ph[mi][ks][rr] = *(uint32_t*)&hh;
                    }
                }
            }

            // ---- O += P V over the 32 keys ----
#pragma unroll
            for (int ks = 0; ks < 2; ks++) {
#pragma unroll
                for (int nd = 0; nd < 4; nd++) {
                    uint32_t vf[4];
                    uint32_t off = swz(koff +
                        (uint32_t)((ks * 16 + vrow) * 128 + nd * 32 + vcb));
                    ldsm_x4_t(vf, kv + FA_V + off);
#pragma unroll
                    for (int mi = 0; mi < 2; mi++) {
                        mma16816h(o[mi][nd * 2],     ph[mi][ks], vf[0], vf[1]);
                        mma16816h(o[mi][nd * 2 + 1], ph[mi][ks], vf[2], vf[3]);
                    }
                }
            }
        }
    }

    // ---- epilogue: reduce l across quad lanes, O / l -> fp16 att ----
    float inv[4];
#pragma unroll
    for (int si = 0; si < 4; si++) {
        float l = ls[si];
        l += __shfl_xor_sync(0xffffffffu, l, 1);
        l += __shfl_xor_sync(0xffffffffu, l, 2);
        inv[si] = 1.f / l;
    }
    const int ecb = h * 64 + (lane & 3) * 2;
#pragma unroll
    for (int mi = 0; mi < 2; mi++) {
        const int er0 = qt * 128 + wid * 32 + mi * 16 + (lane >> 2);
        const size_t row = (size_t)b * T_ + er0;
#pragma unroll
        for (int nj = 0; nj < 8; nj++) {
            *(__half2*)(att + row * C_ + ecb + nj * 8) =
                __floats2half2_rn(o[mi][nj][0] * inv[mi * 2],
                                  o[mi][nj][1] * inv[mi * 2]);
            *(__half2*)(att + (row + 8) * C_ + ecb + nj * 8) =
                __floats2half2_rn(o[mi][nj][2] * inv[mi * 2 + 1],
                                  o[mi][nj][3] * inv[mi * 2 + 1]);
        }
    }
}

// ---------------------------------------------------------------------------
// Launch sequence: prepass -> QKV GEMM -> flash -> proj GEMM
// ---------------------------------------------------------------------------
extern "C" void kernel_launch(void* const* d_in, const int* in_sizes, int n_in,
                              void* d_out, int out_size)
{
    const float* x      = (const float*)d_in[0];
    const float* w_qkv  = (const float*)d_in[1];
    const float* b_qkv  = (const float*)d_in[2];
    const float* w_proj = (const float*)d_in[3];
    const float* b_proj = (const float*)d_in[4];
    float* out = (float*)d_out;

    __half *xh, *wt, *wt2, *qh, *kh, *vh;
    cudaGetSymbolAddress((void**)&xh, g_xh);
    cudaGetSymbolAddress((void**)&wt, g_wt);
    cudaGetSymbolAddress((void**)&wt2, g_wt2);
    cudaGetSymbolAddress((void**)&qh, g_qh);
    cudaGetSymbolAddress((void**)&kh, g_kh);
    cudaGetSymbolAddress((void**)&vh, g_vh);

    cudaFuncSetAttribute(gemm_f16<0>, cudaFuncAttributeMaxDynamicSharedMemorySize, SM_TOTAL);
    cudaFuncSetAttribute(gemm_f16<1>, cudaFuncAttributeMaxDynamicSharedMemorySize, SM_TOTAL);
    cudaFuncSetAttribute(flash_attn, cudaFuncAttributeMaxDynamicSharedMemorySize, FA_TOTAL);

    // 1) fused prepass: x->fp16, w_qkv->W^T fp16, w_proj->W^T fp16
    prepass<<<PRE_TOTAL, 256>>>(x, w_qkv, w_proj, xh, wt, wt2);

    // 2) QKV GEMM -> per-head q (scaled)/k/v fp16
    {
        dim3 grid(N_QKV / 128, M_ROWS / 128);
        gemm_f16<1><<<grid, 256, SM_TOTAL>>>(xh, wt, b_qkv, nullptr,
                                             qh, kh, vh, M_ROWS, N_QKV, C_);
    }
    // 3) flash attention -> fp16 att (reuses xh)
    {
        dim3 grid(T_ / 128, H_, B_);
        flash_attn<<<grid, 128, FA_TOTAL>>>(qh, kh, vh, xh);
    }
    // 4) proj GEMM -> fp32 out (R14 config)
    {
        dim3 grid(C_ / 128, M_ROWS / 128);
        gemm_f16<0><<<grid, 256, SM_TOTAL>>>(xh, wt2, b_proj, out,
                                             nullptr, nullptr, nullptr,
                                             M_ROWS, C_, C_);
    }
}